// round 13
// baseline (speedup 1.0000x reference)
#include <cuda_runtime.h>
#include <cuda_fp16.h>
#include <mma.h>
#include <math.h>

using namespace nvcuda;

#define N_NODES 50000
#define E_EDGES 800000
#define ETOT    (E_EDGES + N_NODES)   // 850000
#define F_IN    128
#define HID     64
#define HEADS   4
#define C1      (HEADS * HID)         // 256
#define SLOPE   0.2f
#define EPS_SM  1e-16f

#define SCAN_T  1024
#define SCAN_CH 52                     // 52*1024 = 53248 >= N_NODES, /4
#define N_PAD   (SCAN_T * SCAN_CH)

// wmma gemm1 tiling
#define G1_BM    64
#define G1_ALD   136
#define G1_WLD   264
#define G1_SLD   264
#define G1_SMEM  ((G1_BM * G1_ALD + 128 * G1_WLD) * 2 > G1_BM * G1_SLD * 4 ? \
                  (G1_BM * G1_ALD + 128 * G1_WLD) * 2 : G1_BM * G1_SLD * 4)

// wmma gemm2 tiling (64 rows x 64 cols x K=256, 4 warps)
#define G2_BM    64
#define G2_ALD   264
#define G2_WLD   72
#define G2_SLD   72
#define G2_SMEM  ((G2_BM * G2_ALD + 256 * G2_WLD) * 2)

// ------------------------- device scratch (no allocs allowed) ---------------
__device__ __half g_h1h[(size_t)N_NODES * C1];    // x @ W1 (fp16 storage)
__device__ __half g_x2h[(size_t)N_NODES * C1];    // layer1 out after LN/ELU (fp16)
__device__ __half g_h2h[(size_t)N_NODES * HID];   // x2 @ W2 (fp16 storage)
__device__ __half g_w1h[F_IN * C1];
__device__ __half g_w2h[C1 * HID];
__device__ float g_s1  [N_NODES * HEADS];
__device__ float g_d1  [N_NODES * HEADS];
__device__ float g_s2  [N_NODES];
__device__ float g_d2  [N_NODES];
// CSR by destination (rebuilt every launch; deterministic work)
__device__ __align__(16) int g_cnt   [N_PAD];
__device__ __align__(16) int g_rowptr[N_PAD + 4];
__device__ __align__(16) int g_wofs  [N_PAD + 4];
__device__ int2 g_epack[ETOT];                    // {src, eid} per CSR slot
// fallback alpha scratch in case d_out layout differs from expectation
__device__ float g_a1_fb[(size_t)ETOT * HEADS];
__device__ float g_a2_fb[(size_t)ETOT];

// ------------------------- helpers ------------------------------------------
__device__ __forceinline__ float lrelu(float v) { return v > 0.f ? v : SLOPE * v; }
__device__ __forceinline__ float eluf(float v)  { return v > 0.f ? v : expm1f(v); }

__device__ __forceinline__ float wredsum(float v) {
#pragma unroll
    for (int o = 16; o > 0; o >>= 1) v += __shfl_xor_sync(0xffffffffu, v, o);
    return v;
}

__device__ __forceinline__ uint2 pack_half4(float4 v) {
    __half2 h0 = __floats2half2_rn(v.x, v.y);
    __half2 h1 = __floats2half2_rn(v.z, v.w);
    return make_uint2(*reinterpret_cast<unsigned*>(&h0),
                      *reinterpret_cast<unsigned*>(&h1));
}

// ------------------------- CSR build -----------------------------------------
__global__ void zero_cnt_kernel() {
    int i = blockIdx.x * blockDim.x + threadIdx.x;
    if (i < N_PAD / 4) *reinterpret_cast<int4*>(&g_cnt[i * 4]) = make_int4(0, 0, 0, 0);
}

__global__ void hist_kernel(const int* __restrict__ ei) {
    int i0 = (blockIdx.x * blockDim.x + threadIdx.x) * 8;
    if (i0 >= ETOT) return;
    if (i0 + 8 <= E_EDGES) {
        int4 d0 = *reinterpret_cast<const int4*>(&ei[E_EDGES + i0]);
        int4 d1 = *reinterpret_cast<const int4*>(&ei[E_EDGES + i0 + 4]);
        atomicAdd(&g_cnt[d0.x], 1); atomicAdd(&g_cnt[d0.y], 1);
        atomicAdd(&g_cnt[d0.z], 1); atomicAdd(&g_cnt[d0.w], 1);
        atomicAdd(&g_cnt[d1.x], 1); atomicAdd(&g_cnt[d1.y], 1);
        atomicAdd(&g_cnt[d1.z], 1); atomicAdd(&g_cnt[d1.w], 1);
    } else {
#pragma unroll
        for (int t = 0; t < 8; t++) {
            int e = i0 + t;
            if (e < ETOT) {
                int dst = (e < E_EDGES) ? ei[E_EDGES + e] : e - E_EDGES;
                atomicAdd(&g_cnt[dst], 1);
            }
        }
    }
}

__global__ __launch_bounds__(SCAN_T) void scan_kernel() {
    __shared__ int sums[SCAN_T];
    int t = threadIdx.x;
    int lo = t * SCAN_CH;
    const int4* cp = reinterpret_cast<const int4*>(&g_cnt[lo]);
    int local = 0;
#pragma unroll
    for (int i = 0; i < SCAN_CH / 4; i++) {
        int4 c = cp[i];
        local += c.x + c.y + c.z + c.w;
    }
    sums[t] = local;
    __syncthreads();
    for (int off = 1; off < SCAN_T; off <<= 1) {
        int v = (t >= off) ? sums[t - off] : 0;
        __syncthreads();
        sums[t] += v;
        __syncthreads();
    }
    int run = sums[t] - local;
    int4* rp = reinterpret_cast<int4*>(&g_rowptr[lo]);
    int4* wp = reinterpret_cast<int4*>(&g_wofs[lo]);
#pragma unroll
    for (int i = 0; i < SCAN_CH / 4; i++) {
        int4 c = cp[i];
        int4 o;
        o.x = run; run += c.x;
        o.y = run; run += c.y;
        o.z = run; run += c.z;
        o.w = run; run += c.w;
        rp[i] = o; wp[i] = o;
    }
}

__global__ void scatter_kernel(const int* __restrict__ ei) {
    int i0 = (blockIdx.x * blockDim.x + threadIdx.x) * 8;
    if (i0 >= ETOT) return;
    if (i0 + 8 <= E_EDGES) {
        int4 s0 = *reinterpret_cast<const int4*>(&ei[i0]);
        int4 s1 = *reinterpret_cast<const int4*>(&ei[i0 + 4]);
        int4 d0 = *reinterpret_cast<const int4*>(&ei[E_EDGES + i0]);
        int4 d1 = *reinterpret_cast<const int4*>(&ei[E_EDGES + i0 + 4]);
        int sl;
        sl = atomicAdd(&g_wofs[d0.x], 1); g_epack[sl] = make_int2(s0.x, i0);
        sl = atomicAdd(&g_wofs[d0.y], 1); g_epack[sl] = make_int2(s0.y, i0 + 1);
        sl = atomicAdd(&g_wofs[d0.z], 1); g_epack[sl] = make_int2(s0.z, i0 + 2);
        sl = atomicAdd(&g_wofs[d0.w], 1); g_epack[sl] = make_int2(s0.w, i0 + 3);
        sl = atomicAdd(&g_wofs[d1.x], 1); g_epack[sl] = make_int2(s1.x, i0 + 4);
        sl = atomicAdd(&g_wofs[d1.y], 1); g_epack[sl] = make_int2(s1.y, i0 + 5);
        sl = atomicAdd(&g_wofs[d1.z], 1); g_epack[sl] = make_int2(s1.z, i0 + 6);
        sl = atomicAdd(&g_wofs[d1.w], 1); g_epack[sl] = make_int2(s1.w, i0 + 7);
    } else {
#pragma unroll
        for (int t = 0; t < 8; t++) {
            int e = i0 + t;
            if (e < ETOT) {
                int src, dst;
                if (e < E_EDGES) { src = ei[e]; dst = ei[E_EDGES + e]; }
                else             { src = dst = e - E_EDGES; }
                int slot = atomicAdd(&g_wofs[dst], 1);
                g_epack[slot] = make_int2(src, e);
            }
        }
    }
}

// ------------------------- W1+W2 fp32 -> fp16 (once per launch) --------------
__global__ void conv_w_kernel(const float* __restrict__ W1,
                              const float* __restrict__ W2) {
    int i4 = (blockIdx.x * blockDim.x + threadIdx.x) * 4;
    if (i4 < F_IN * C1) {
        float4 v = *reinterpret_cast<const float4*>(&W1[i4]);
        *reinterpret_cast<uint2*>(&g_w1h[i4]) = pack_half4(v);
    } else if (i4 < F_IN * C1 + C1 * HID) {
        int j4 = i4 - F_IN * C1;
        float4 v = *reinterpret_cast<const float4*>(&W2[j4]);
        *reinterpret_cast<uint2*>(&g_w2h[j4]) = pack_half4(v);
    }
}

// ---- layer-1 GEMM on tensor cores (HMMA) + fused logits ---------------------
__global__ __launch_bounds__(256)
void gemm1_wmma_kernel(const float* __restrict__ X,
                       const float* __restrict__ asrc, const float* __restrict__ adst,
                       __half* __restrict__ Yh,
                       float* __restrict__ S, float* __restrict__ D, int nrows) {
    extern __shared__ char smraw[];
    __half* Ah  = reinterpret_cast<__half*>(smraw);
    __half* Wh  = reinterpret_cast<__half*>(smraw) + G1_BM * G1_ALD;
    float*  stg = reinterpret_cast<float*>(smraw);

    int tid = threadIdx.x;
    int rowbase = blockIdx.x * G1_BM;

    for (int i = tid * 4; i < G1_BM * F_IN; i += 256 * 4) {
        int r = i >> 7, c = i & 127;
        int gr = rowbase + r;
        float4 v = (gr < nrows) ? *reinterpret_cast<const float4*>(&X[(size_t)gr * F_IN + c])
                                : make_float4(0.f, 0.f, 0.f, 0.f);
        *reinterpret_cast<uint2*>(&Ah[r * G1_ALD + c]) = pack_half4(v);
    }
    for (int i = tid * 8; i < F_IN * C1; i += 256 * 8) {
        int k = i >> 8, c = i & 255;
        uint4 v = *reinterpret_cast<const uint4*>(&g_w1h[i]);
        *reinterpret_cast<uint4*>(&Wh[k * G1_WLD + c]) = v;
    }
    __syncthreads();

    int w = tid >> 5;
    int r0 = (w & 3) * 16;
    int cb = (w >> 2) * 128;

    wmma::fragment<wmma::accumulator, 16, 16, 16, float> acc[8];
#pragma unroll
    for (int f = 0; f < 8; f++) wmma::fill_fragment(acc[f], 0.f);

#pragma unroll
    for (int kk = 0; kk < F_IN; kk += 16) {
        wmma::fragment<wmma::matrix_a, 16, 16, 16, __half, wmma::row_major> af;
        wmma::load_matrix_sync(af, Ah + r0 * G1_ALD + kk, G1_ALD);
#pragma unroll
        for (int f = 0; f < 8; f++) {
            wmma::fragment<wmma::matrix_b, 16, 16, 16, __half, wmma::row_major> bf;
            wmma::load_matrix_sync(bf, Wh + kk * G1_WLD + cb + f * 16, G1_WLD);
            wmma::mma_sync(acc[f], af, bf, acc[f]);
        }
    }
    __syncthreads();
#pragma unroll
    for (int f = 0; f < 8; f++)
        wmma::store_matrix_sync(stg + r0 * G1_SLD + cb + f * 16, acc[f],
                                G1_SLD, wmma::mem_row_major);
    __syncthreads();

    int r = tid >> 2, q = tid & 3;
    int gr = rowbase + r;
    if (gr < nrows) {
        const float* as = asrc + q * 64;
        const float* ad = adst + q * 64;
        const float* row = stg + r * G1_SLD + q * 64;
        __half* yp = Yh + (size_t)gr * C1 + q * 64;
        float s = 0.f, dd = 0.f;
#pragma unroll
        for (int i = 0; i < 64; i += 4) {
            float4 v = *reinterpret_cast<const float4*>(&row[i]);
            float4 a = *reinterpret_cast<const float4*>(&as[i]);
            float4 b = *reinterpret_cast<const float4*>(&ad[i]);
            s  += v.x * a.x + v.y * a.y + v.z * a.z + v.w * a.w;
            dd += v.x * b.x + v.y * b.y + v.z * b.z + v.w * b.w;
            *reinterpret_cast<uint2*>(&yp[i]) = pack_half4(v);
        }
        S[gr * 4 + q] = s;
        D[gr * 4 + q] = dd;
    }
}

// ---- layer-2 GEMM on tensor cores (HMMA) + fused logits ---------------------
// A (= x2) already fp16: straight copy into smem, no conversion.
__global__ __launch_bounds__(128)
void gemm2_wmma_kernel(const __half* __restrict__ Xh,
                       const float* __restrict__ asrc, const float* __restrict__ adst,
                       __half* __restrict__ Yh,
                       float* __restrict__ S, float* __restrict__ D, int nrows) {
    extern __shared__ char smraw[];
    __half* Ah  = reinterpret_cast<__half*>(smraw);
    __half* Wh  = reinterpret_cast<__half*>(smraw) + G2_BM * G2_ALD;
    float*  stg = reinterpret_cast<float*>(smraw);

    int tid = threadIdx.x;
    int rowbase = blockIdx.x * G2_BM;

    for (int i = tid * 8; i < G2_BM * C1; i += 128 * 8) {
        int r = i >> 8, c = i & 255;
        int gr = rowbase + r;
        uint4 v = (gr < nrows)
            ? *reinterpret_cast<const uint4*>(&Xh[(size_t)gr * C1 + c])
            : make_uint4(0u, 0u, 0u, 0u);
        *reinterpret_cast<uint4*>(&Ah[r * G2_ALD + c]) = v;
    }
    for (int i = tid * 8; i < C1 * HID; i += 128 * 8) {
        int k = i >> 6, c = i & 63;
        uint4 v = *reinterpret_cast<const uint4*>(&g_w2h[i]);
        *reinterpret_cast<uint4*>(&Wh[k * G2_WLD + c]) = v;
    }
    __syncthreads();

    int w = tid >> 5;
    int r0 = w * 16;

    wmma::fragment<wmma::accumulator, 16, 16, 16, float> acc[4];
#pragma unroll
    for (int f = 0; f < 4; f++) wmma::fill_fragment(acc[f], 0.f);

#pragma unroll
    for (int kk = 0; kk < C1; kk += 16) {
        wmma::fragment<wmma::matrix_a, 16, 16, 16, __half, wmma::row_major> af;
        wmma::load_matrix_sync(af, Ah + r0 * G2_ALD + kk, G2_ALD);
#pragma unroll
        for (int f = 0; f < 4; f++) {
            wmma::fragment<wmma::matrix_b, 16, 16, 16, __half, wmma::row_major> bf;
            wmma::load_matrix_sync(bf, Wh + kk * G2_WLD + f * 16, G2_WLD);
            wmma::mma_sync(acc[f], af, bf, acc[f]);
        }
    }
    __syncthreads();
#pragma unroll
    for (int f = 0; f < 4; f++)
        wmma::store_matrix_sync(stg + r0 * G2_SLD + f * 16, acc[f],
                                G2_SLD, wmma::mem_row_major);
    __syncthreads();

    int r = tid >> 1, half = tid & 1;
    int c0 = half * 32;
    int gr = rowbase + r;
    float s = 0.f, dd = 0.f;
    if (gr < nrows) {
        const float* row = stg + r * G2_SLD + c0;
        __half* yp = Yh + (size_t)gr * HID + c0;
#pragma unroll
        for (int i = 0; i < 32; i += 4) {
            float4 v = *reinterpret_cast<const float4*>(&row[i]);
            float4 a = *reinterpret_cast<const float4*>(&asrc[c0 + i]);
            float4 b = *reinterpret_cast<const float4*>(&adst[c0 + i]);
            s  += v.x * a.x + v.y * a.y + v.z * a.z + v.w * a.w;
            dd += v.x * b.x + v.y * b.y + v.z * b.z + v.w * b.w;
            *reinterpret_cast<uint2*>(&yp[i]) = pack_half4(v);
        }
    }
    s  += __shfl_xor_sync(0xffffffffu, s, 1);
    dd += __shfl_xor_sync(0xffffffffu, dd, 1);
    if (gr < nrows && half == 0) { S[gr] = s; D[gr] = dd; }
}

// ------------------------- layer 1: chunked gather + LN + ELU ----------------
// Pre-pass (lane-parallel): exps computed ONCE per edge, parked in smem;
// inner loop per edge: shfl(src) + LDS(e) + LDG.128 + 8 FMA.
__global__ __launch_bounds__(256)
void agg1_kernel(float* __restrict__ a1, const float* __restrict__ b1,
                 const float* __restrict__ gam, const float* __restrict__ bet) {
    __shared__ float4 se[8][32];
    int wid  = threadIdx.x >> 5;
    int lane = threadIdx.x & 31;
    int n    = (blockIdx.x * blockDim.x + threadIdx.x) >> 5;
    if (n >= N_NODES) return;
    int base = g_rowptr[n], end = g_rowptr[n + 1];
    float4 d = *reinterpret_cast<const float4*>(&g_d1[n * 4]);

    int h  = lane >> 3;
    int c0 = lane * 8;
    float acc[8];
#pragma unroll
    for (int i = 0; i < 8; i++) acc[i] = 0.f;
    float4 den = make_float4(0.f, 0.f, 0.f, 0.f);

    for (int cb = base; cb < end; cb += 32) {
        int cnt = min(32, end - cb);
        int my_src = 0;
        if (lane < cnt) {
            int2 p = g_epack[cb + lane];               // coalesced
            my_src = p.x;
            float4 s = *reinterpret_cast<const float4*>(&g_s1[p.x * 4]);
            float4 e;
            e.x = __expf(lrelu(s.x + d.x)); e.y = __expf(lrelu(s.y + d.y));
            e.z = __expf(lrelu(s.z + d.z)); e.w = __expf(lrelu(s.w + d.w));
            den.x += e.x; den.y += e.y; den.z += e.z; den.w += e.w;
            se[wid][lane] = e;
        }
        __syncwarp();
        for (int k = 0; k < cnt; k++) {
            int src  = __shfl_sync(0xffffffffu, my_src, k);
            float a  = reinterpret_cast<const float*>(&se[wid][k])[h];
            uint4 hv = *reinterpret_cast<const uint4*>(&g_h1h[(size_t)src * C1 + c0]);
            float2 f0 = __half22float2(*reinterpret_cast<__half2*>(&hv.x));
            float2 f1 = __half22float2(*reinterpret_cast<__half2*>(&hv.y));
            float2 f2 = __half22float2(*reinterpret_cast<__half2*>(&hv.z));
            float2 f3 = __half22float2(*reinterpret_cast<__half2*>(&hv.w));
            acc[0] += f0.x * a; acc[1] += f0.y * a;
            acc[2] += f1.x * a; acc[3] += f1.y * a;
            acc[4] += f2.x * a; acc[5] += f2.y * a;
            acc[6] += f3.x * a; acc[7] += f3.y * a;
        }
        __syncwarp();
    }

    den.x = wredsum(den.x); den.y = wredsum(den.y);
    den.z = wredsum(den.z); den.w = wredsum(den.w);
    float4 inv = make_float4(1.f / (den.x + EPS_SM), 1.f / (den.y + EPS_SM),
                             1.f / (den.z + EPS_SM), 1.f / (den.w + EPS_SM));

    // alpha writes, lane-parallel
    for (int jj = base + lane; jj < end; jj += 32) {
        int2 p = g_epack[jj];
        float4 s = *reinterpret_cast<const float4*>(&g_s1[p.x * 4]);
        float4 al;
        al.x = __expf(lrelu(s.x + d.x)) * inv.x;
        al.y = __expf(lrelu(s.y + d.y)) * inv.y;
        al.z = __expf(lrelu(s.z + d.z)) * inv.z;
        al.w = __expf(lrelu(s.w + d.w)) * inv.w;
        *reinterpret_cast<float4*>(&a1[(size_t)p.y * 4]) = al;
    }

    float invh = (h == 0) ? inv.x : (h == 1) ? inv.y : (h == 2) ? inv.z : inv.w;
#pragma unroll
    for (int i = 0; i < 8; i++) acc[i] *= invh;

    // epilogue: +b1, LayerNorm(256), ELU -> g_x2h (fp16; equivalent to gemm2's own rounding)
    float4 ba = *reinterpret_cast<const float4*>(&b1[c0]);
    float4 bb = *reinterpret_cast<const float4*>(&b1[c0 + 4]);
    acc[0] += ba.x; acc[1] += ba.y; acc[2] += ba.z; acc[3] += ba.w;
    acc[4] += bb.x; acc[5] += bb.y; acc[6] += bb.z; acc[7] += bb.w;
    float sum = 0.f, sq = 0.f;
#pragma unroll
    for (int i = 0; i < 8; i++) { sum += acc[i]; sq += acc[i] * acc[i]; }
    sum = wredsum(sum); sq = wredsum(sq);
    float mu  = sum * (1.f / 256.f);
    float var = sq * (1.f / 256.f) - mu * mu;
    float rs  = rsqrtf(var + 1e-5f);
    float4 ga = *reinterpret_cast<const float4*>(&gam[c0]);
    float4 gb = *reinterpret_cast<const float4*>(&gam[c0 + 4]);
    float4 ea = *reinterpret_cast<const float4*>(&bet[c0]);
    float4 eb = *reinterpret_cast<const float4*>(&bet[c0 + 4]);
    float4 y0, y1;
    y0.x = eluf((acc[0] - mu) * rs * ga.x + ea.x);
    y0.y = eluf((acc[1] - mu) * rs * ga.y + ea.y);
    y0.z = eluf((acc[2] - mu) * rs * ga.z + ea.z);
    y0.w = eluf((acc[3] - mu) * rs * ga.w + ea.w);
    y1.x = eluf((acc[4] - mu) * rs * gb.x + eb.x);
    y1.y = eluf((acc[5] - mu) * rs * gb.y + eb.y);
    y1.z = eluf((acc[6] - mu) * rs * gb.z + eb.z);
    y1.w = eluf((acc[7] - mu) * rs * gb.w + eb.w);
    uint2 p0 = pack_half4(y0);
    uint2 p1 = pack_half4(y1);
    *reinterpret_cast<uint4*>(&g_x2h[(size_t)n * C1 + c0]) =
        make_uint4(p0.x, p0.y, p1.x, p1.y);
}

// ------------------------- layer 2: chunked gather + LN + ELU + head ---------
// Pre-pass exps lane-parallel; inner loop: 2 SHFL + LDG + 2 FMA. No extra smem.
__global__ __launch_bounds__(256)
void agg2_kernel(float* __restrict__ a2, const float* __restrict__ b2,
                 const float* __restrict__ g2, const float* __restrict__ e2,
                 const float* __restrict__ hW1, const float* __restrict__ hb1,
                 const float* __restrict__ hW2, const float* __restrict__ hb2,
                 float* __restrict__ out) {
    __shared__ float w1s[64 * 32];
    __shared__ float w2s[32];
    __shared__ float b1s[32];
    __shared__ float zs[8][64];
    int tid = threadIdx.x;
    for (int i = tid; i < 64 * 32; i += 256) w1s[i] = hW1[i];
    if (tid < 32) { w2s[tid] = hW2[tid]; b1s[tid] = hb1[tid]; }
    __syncthreads();

    int w    = tid >> 5;
    int lane = tid & 31;
    int n = blockIdx.x * 8 + w;
    if (n >= N_NODES) return;

    int base = g_rowptr[n], end = g_rowptr[n + 1];
    float dd = g_d2[n];

    float a0 = 0.f, a1v = 0.f, den = 0.f;
    int c0 = lane * 2;
    for (int cb = base; cb < end; cb += 32) {
        int cnt = min(32, end - cb);
        int my_src = 0; float my_e = 0.f;
        if (lane < cnt) {
            int2 p = g_epack[cb + lane];               // coalesced
            my_src = p.x;
            my_e = __expf(lrelu(g_s2[p.x] + dd));
            den += my_e;
        }
        for (int k = 0; k < cnt; k++) {
            int src = __shfl_sync(0xffffffffu, my_src, k);
            float e = __shfl_sync(0xffffffffu, my_e, k);
            unsigned u = *reinterpret_cast<const unsigned*>(&g_h2h[(size_t)src * HID + c0]);
            float2 v = __half22float2(*reinterpret_cast<__half2*>(&u));
            a0 += v.x * e; a1v += v.y * e;
        }
    }
    den = wredsum(den);
    float inv = 1.f / (den + EPS_SM);

    for (int jj = base + lane; jj < end; jj += 32) {
        int2 p = g_epack[jj];
        a2[p.y] = __expf(lrelu(g_s2[p.x] + dd)) * inv;
    }
    a0 *= inv; a1v *= inv;

    // +b2, LN(64), ELU
    a0  += b2[c0];
    a1v += b2[c0 + 1];
    float sum = wredsum(a0 + a1v);
    float sq  = wredsum(a0 * a0 + a1v * a1v);
    float mu  = sum * (1.f / 64.f);
    float var = sq * (1.f / 64.f) - mu * mu;
    float rs  = rsqrtf(var + 1e-5f);
    float y0 = eluf((a0  - mu) * rs * g2[c0]     + e2[c0]);
    float y1 = eluf((a1v - mu) * rs * g2[c0 + 1] + e2[c0 + 1]);
    zs[w][c0] = y0; zs[w][c0 + 1] = y1;
    __syncwarp();

    // MLP head: 64 -> 32 -> ReLU -> 1
    float acc = b1s[lane];
#pragma unroll
    for (int k = 0; k < 64; k++) acc += zs[w][k] * w1s[k * 32 + lane];
    acc = fmaxf(acc, 0.f);
    float p = wredsum(acc * w2s[lane]);
    if (lane == 0) out[n] = p + hb2[0];
}

// ------------------------- host launcher -------------------------------------
extern "C" void kernel_launch(void* const* d_in, const int* in_sizes, int n_in,
                              void* d_out, int out_size) {
    const float* x     = (const float*)d_in[0];
    const int*   ei    = (const int*)  d_in[1];
    const float* W1    = (const float*)d_in[2];
    const float* as1   = (const float*)d_in[3];
    const float* ad1   = (const float*)d_in[4];
    const float* b1    = (const float*)d_in[5];
    const float* W2    = (const float*)d_in[6];
    const float* as2   = (const float*)d_in[7];
    const float* ad2   = (const float*)d_in[8];
    const float* b2    = (const float*)d_in[9];
    const float* ln1g  = (const float*)d_in[10];
    const float* ln1b  = (const float*)d_in[11];
    const float* ln2g  = (const float*)d_in[12];
    const float* ln2b  = (const float*)d_in[13];
    const float* hW1   = (const float*)d_in[14];
    const float* hb1   = (const float*)d_in[15];
    const float* hW2   = (const float*)d_in[16];
    const float* hb2   = (const float*)d_in[17];
    float* out = (float*)d_out;

    // expected layout: out[N] | alpha1[ETOT*4] | alpha2[ETOT]
    size_t need = (size_t)N_NODES + (size_t)ETOT * (HEADS + 1);
    float *a1, *a2;
    if ((size_t)out_size >= need) {
        a1 = out + N_NODES;
        a2 = a1 + (size_t)ETOT * HEADS;
    } else {
        void* p;
        cudaGetSymbolAddress(&p, g_a1_fb); a1 = (float*)p;
        cudaGetSymbolAddress(&p, g_a2_fb); a2 = (float*)p;
    }

    auto cdiv = [](long a, long b) { return (int)((a + b - 1) / b); };

    float *ps1, *pd1, *ps2, *pd2;
    __half *ph1, *px2, *ph2;
    { void* p;
      cudaGetSymbolAddress(&p, g_h1h); ph1 = (__half*)p;
      cudaGetSymbolAddress(&p, g_x2h); px2 = (__half*)p;
      cudaGetSymbolAddress(&p, g_h2h); ph2 = (__half*)p;
      cudaGetSymbolAddress(&p, g_s1);  ps1 = (float*)p;
      cudaGetSymbolAddress(&p, g_d1);  pd1 = (float*)p;
      cudaGetSymbolAddress(&p, g_s2);  ps2 = (float*)p;
      cudaGetSymbolAddress(&p, g_d2);  pd2 = (float*)p;
    }

    cudaFuncSetAttribute(gemm1_wmma_kernel,
                         cudaFuncAttributeMaxDynamicSharedMemorySize, G1_SMEM);
    cudaFuncSetAttribute(gemm2_wmma_kernel,
                         cudaFuncAttributeMaxDynamicSharedMemorySize, G2_SMEM);

    // side stream for the CSR build (fork-join; both branches rejoin before agg1)
    cudaStream_t side;
    cudaStreamCreateWithFlags(&side, cudaStreamNonBlocking);
    cudaEvent_t evF, evJ;
    cudaEventCreateWithFlags(&evF, cudaEventDisableTiming);
    cudaEventCreateWithFlags(&evJ, cudaEventDisableTiming);

    cudaEventRecord(evF, 0);
    cudaStreamWaitEvent(side, evF, 0);

    // ---- CSR build on side stream (independent of GEMM1) ----
    zero_cnt_kernel<<<cdiv(N_PAD / 4, 256), 256, 0, side>>>();
    hist_kernel<<<cdiv(cdiv(ETOT, 8), 256), 256, 0, side>>>(ei);
    scan_kernel<<<1, SCAN_T, 0, side>>>();
    scatter_kernel<<<cdiv(cdiv(ETOT, 8), 256), 256, 0, side>>>(ei);
    cudaEventRecord(evJ, side);

    // ---- layer 1: W1/W2->fp16, then HMMA GEMM + fused logits (main stream) ----
    conv_w_kernel<<<cdiv((F_IN * C1 + C1 * HID) / 4, 256), 256>>>(W1, W2);
    gemm1_wmma_kernel<<<cdiv(N_NODES, G1_BM), 256, G1_SMEM>>>(
        x, as1, ad1, ph1, ps1, pd1, N_NODES);

    cudaStreamWaitEvent(0, evJ, 0);     // join: agg1 needs CSR + h1 + s1/d1
    agg1_kernel<<<cdiv((long)N_NODES * 32, 256), 256>>>(a1, b1, ln1g, ln1b);

    // ---- layer 2: HMMA GEMM + fused logits ----
    gemm2_wmma_kernel<<<cdiv(N_NODES, G2_BM), 128, G2_SMEM>>>(
        px2, as2, ad2, ph2, ps2, pd2, N_NODES);
    agg2_kernel<<<cdiv(N_NODES, 8), 256>>>(a2, b2, ln2g, ln2b, hW1, hb1, hW2, hb2, out);
}

// round 14
// speedup vs baseline: 1.0227x; 1.0227x over previous
#include <cuda_runtime.h>
#include <cuda_fp16.h>
#include <mma.h>
#include <math.h>

using namespace nvcuda;

#define N_NODES 50000
#define E_EDGES 800000
#define ETOT    (E_EDGES + N_NODES)   // 850000
#define F_IN    128
#define HID     64
#define HEADS   4
#define C1      (HEADS * HID)         // 256
#define SLOPE   0.2f
#define EPS_SM  1e-16f

#define SCAN_T  1024
#define SCAN_CH 52                     // 52*1024 = 53248 >= N_NODES, /4
#define N_PAD   (SCAN_T * SCAN_CH)

// wmma gemm1 tiling
#define G1_BM    64
#define G1_ALD   136
#define G1_WLD   264
#define G1_SLD   264
#define G1_SMEM  ((G1_BM * G1_ALD + 128 * G1_WLD) * 2 > G1_BM * G1_SLD * 4 ? \
                  (G1_BM * G1_ALD + 128 * G1_WLD) * 2 : G1_BM * G1_SLD * 4)

// wmma gemm2 tiling (64 rows x 64 cols x K=256, 4 warps)
#define G2_BM    64
#define G2_ALD   264
#define G2_WLD   72
#define G2_SLD   72
#define G2_SMEM  ((G2_BM * G2_ALD + 256 * G2_WLD) * 2)

// ------------------------- device scratch (no allocs allowed) ---------------
__device__ __half g_h1h[(size_t)N_NODES * C1];    // x @ W1 (fp16 storage)
__device__ __half g_x2h[(size_t)N_NODES * C1];    // layer1 out after LN/ELU (fp16)
__device__ __half g_h2h[(size_t)N_NODES * HID];   // x2 @ W2 (fp16 storage)
__device__ __half g_w1h[F_IN * C1];
__device__ __half g_w2h[C1 * HID];
__device__ float g_s1  [N_NODES * HEADS];
__device__ float g_d1  [N_NODES * HEADS];
__device__ float g_s2  [N_NODES];
__device__ float g_d2  [N_NODES];
// CSR by destination (rebuilt every launch; deterministic work)
__device__ __align__(16) int g_cnt   [N_PAD];
__device__ __align__(16) int g_rowptr[N_PAD + 4];
__device__ __align__(16) int g_wofs  [N_PAD + 4];
__device__ int2 g_epack[ETOT];                    // {src, eid} per CSR slot
// fallback alpha scratch in case d_out layout differs from expectation
__device__ float g_a1_fb[(size_t)ETOT * HEADS];
__device__ float g_a2_fb[(size_t)ETOT];

// ------------------------- helpers ------------------------------------------
__device__ __forceinline__ float lrelu(float v) { return v > 0.f ? v : SLOPE * v; }
__device__ __forceinline__ float eluf(float v)  { return v > 0.f ? v : expm1f(v); }

__device__ __forceinline__ float wredsum(float v) {
#pragma unroll
    for (int o = 16; o > 0; o >>= 1) v += __shfl_xor_sync(0xffffffffu, v, o);
    return v;
}

__device__ __forceinline__ uint2 pack_half4(float4 v) {
    __half2 h0 = __floats2half2_rn(v.x, v.y);
    __half2 h1 = __floats2half2_rn(v.z, v.w);
    return make_uint2(*reinterpret_cast<unsigned*>(&h0),
                      *reinterpret_cast<unsigned*>(&h1));
}

// ------------------------- CSR build -----------------------------------------
__global__ void zero_cnt_kernel() {
    int i = blockIdx.x * blockDim.x + threadIdx.x;
    if (i < N_PAD / 4) *reinterpret_cast<int4*>(&g_cnt[i * 4]) = make_int4(0, 0, 0, 0);
}

__global__ void hist_kernel(const int* __restrict__ ei) {
    int i0 = (blockIdx.x * blockDim.x + threadIdx.x) * 8;
    if (i0 >= ETOT) return;
    if (i0 + 8 <= E_EDGES) {
        int4 d0 = *reinterpret_cast<const int4*>(&ei[E_EDGES + i0]);
        int4 d1 = *reinterpret_cast<const int4*>(&ei[E_EDGES + i0 + 4]);
        atomicAdd(&g_cnt[d0.x], 1); atomicAdd(&g_cnt[d0.y], 1);
        atomicAdd(&g_cnt[d0.z], 1); atomicAdd(&g_cnt[d0.w], 1);
        atomicAdd(&g_cnt[d1.x], 1); atomicAdd(&g_cnt[d1.y], 1);
        atomicAdd(&g_cnt[d1.z], 1); atomicAdd(&g_cnt[d1.w], 1);
    } else {
#pragma unroll
        for (int t = 0; t < 8; t++) {
            int e = i0 + t;
            if (e < ETOT) {
                int dst = (e < E_EDGES) ? ei[E_EDGES + e] : e - E_EDGES;
                atomicAdd(&g_cnt[dst], 1);
            }
        }
    }
}

__global__ __launch_bounds__(SCAN_T) void scan_kernel() {
    __shared__ int sums[SCAN_T];
    int t = threadIdx.x;
    int lo = t * SCAN_CH;
    const int4* cp = reinterpret_cast<const int4*>(&g_cnt[lo]);
    int local = 0;
#pragma unroll
    for (int i = 0; i < SCAN_CH / 4; i++) {
        int4 c = cp[i];
        local += c.x + c.y + c.z + c.w;
    }
    sums[t] = local;
    __syncthreads();
    for (int off = 1; off < SCAN_T; off <<= 1) {
        int v = (t >= off) ? sums[t - off] : 0;
        __syncthreads();
        sums[t] += v;
        __syncthreads();
    }
    int run = sums[t] - local;
    int4* rp = reinterpret_cast<int4*>(&g_rowptr[lo]);
    int4* wp = reinterpret_cast<int4*>(&g_wofs[lo]);
#pragma unroll
    for (int i = 0; i < SCAN_CH / 4; i++) {
        int4 c = cp[i];
        int4 o;
        o.x = run; run += c.x;
        o.y = run; run += c.y;
        o.z = run; run += c.z;
        o.w = run; run += c.w;
        rp[i] = o; wp[i] = o;
    }
}

__global__ void scatter_kernel(const int* __restrict__ ei) {
    int i0 = (blockIdx.x * blockDim.x + threadIdx.x) * 8;
    if (i0 >= ETOT) return;
    if (i0 + 8 <= E_EDGES) {
        int4 s0 = *reinterpret_cast<const int4*>(&ei[i0]);
        int4 s1 = *reinterpret_cast<const int4*>(&ei[i0 + 4]);
        int4 d0 = *reinterpret_cast<const int4*>(&ei[E_EDGES + i0]);
        int4 d1 = *reinterpret_cast<const int4*>(&ei[E_EDGES + i0 + 4]);
        int sl;
        sl = atomicAdd(&g_wofs[d0.x], 1); g_epack[sl] = make_int2(s0.x, i0);
        sl = atomicAdd(&g_wofs[d0.y], 1); g_epack[sl] = make_int2(s0.y, i0 + 1);
        sl = atomicAdd(&g_wofs[d0.z], 1); g_epack[sl] = make_int2(s0.z, i0 + 2);
        sl = atomicAdd(&g_wofs[d0.w], 1); g_epack[sl] = make_int2(s0.w, i0 + 3);
        sl = atomicAdd(&g_wofs[d1.x], 1); g_epack[sl] = make_int2(s1.x, i0 + 4);
        sl = atomicAdd(&g_wofs[d1.y], 1); g_epack[sl] = make_int2(s1.y, i0 + 5);
        sl = atomicAdd(&g_wofs[d1.z], 1); g_epack[sl] = make_int2(s1.z, i0 + 6);
        sl = atomicAdd(&g_wofs[d1.w], 1); g_epack[sl] = make_int2(s1.w, i0 + 7);
    } else {
#pragma unroll
        for (int t = 0; t < 8; t++) {
            int e = i0 + t;
            if (e < ETOT) {
                int src, dst;
                if (e < E_EDGES) { src = ei[e]; dst = ei[E_EDGES + e]; }
                else             { src = dst = e - E_EDGES; }
                int slot = atomicAdd(&g_wofs[dst], 1);
                g_epack[slot] = make_int2(src, e);
            }
        }
    }
}

// ------------------------- W1+W2 fp32 -> fp16 (once per launch) --------------
__global__ void conv_w_kernel(const float* __restrict__ W1,
                              const float* __restrict__ W2) {
    int i4 = (blockIdx.x * blockDim.x + threadIdx.x) * 4;
    if (i4 < F_IN * C1) {
        float4 v = *reinterpret_cast<const float4*>(&W1[i4]);
        *reinterpret_cast<uint2*>(&g_w1h[i4]) = pack_half4(v);
    } else if (i4 < F_IN * C1 + C1 * HID) {
        int j4 = i4 - F_IN * C1;
        float4 v = *reinterpret_cast<const float4*>(&W2[j4]);
        *reinterpret_cast<uint2*>(&g_w2h[j4]) = pack_half4(v);
    }
}

// ---- layer-1 GEMM on tensor cores (HMMA) + fused logits ---------------------
__global__ __launch_bounds__(256)
void gemm1_wmma_kernel(const float* __restrict__ X,
                       const float* __restrict__ asrc, const float* __restrict__ adst,
                       __half* __restrict__ Yh,
                       float* __restrict__ S, float* __restrict__ D, int nrows) {
    extern __shared__ char smraw[];
    __half* Ah  = reinterpret_cast<__half*>(smraw);
    __half* Wh  = reinterpret_cast<__half*>(smraw) + G1_BM * G1_ALD;
    float*  stg = reinterpret_cast<float*>(smraw);

    int tid = threadIdx.x;
    int rowbase = blockIdx.x * G1_BM;

    for (int i = tid * 4; i < G1_BM * F_IN; i += 256 * 4) {
        int r = i >> 7, c = i & 127;
        int gr = rowbase + r;
        float4 v = (gr < nrows) ? *reinterpret_cast<const float4*>(&X[(size_t)gr * F_IN + c])
                                : make_float4(0.f, 0.f, 0.f, 0.f);
        *reinterpret_cast<uint2*>(&Ah[r * G1_ALD + c]) = pack_half4(v);
    }
    for (int i = tid * 8; i < F_IN * C1; i += 256 * 8) {
        int k = i >> 8, c = i & 255;
        uint4 v = *reinterpret_cast<const uint4*>(&g_w1h[i]);
        *reinterpret_cast<uint4*>(&Wh[k * G1_WLD + c]) = v;
    }
    __syncthreads();

    int w = tid >> 5;
    int r0 = (w & 3) * 16;
    int cb = (w >> 2) * 128;

    wmma::fragment<wmma::accumulator, 16, 16, 16, float> acc[8];
#pragma unroll
    for (int f = 0; f < 8; f++) wmma::fill_fragment(acc[f], 0.f);

#pragma unroll
    for (int kk = 0; kk < F_IN; kk += 16) {
        wmma::fragment<wmma::matrix_a, 16, 16, 16, __half, wmma::row_major> af;
        wmma::load_matrix_sync(af, Ah + r0 * G1_ALD + kk, G1_ALD);
#pragma unroll
        for (int f = 0; f < 8; f++) {
            wmma::fragment<wmma::matrix_b, 16, 16, 16, __half, wmma::row_major> bf;
            wmma::load_matrix_sync(bf, Wh + kk * G1_WLD + cb + f * 16, G1_WLD);
            wmma::mma_sync(acc[f], af, bf, acc[f]);
        }
    }
    __syncthreads();
#pragma unroll
    for (int f = 0; f < 8; f++)
        wmma::store_matrix_sync(stg + r0 * G1_SLD + cb + f * 16, acc[f],
                                G1_SLD, wmma::mem_row_major);
    __syncthreads();

    int r = tid >> 2, q = tid & 3;
    int gr = rowbase + r;
    if (gr < nrows) {
        const float* as = asrc + q * 64;
        const float* ad = adst + q * 64;
        const float* row = stg + r * G1_SLD + q * 64;
        __half* yp = Yh + (size_t)gr * C1 + q * 64;
        float s = 0.f, dd = 0.f;
#pragma unroll
        for (int i = 0; i < 64; i += 4) {
            float4 v = *reinterpret_cast<const float4*>(&row[i]);
            float4 a = *reinterpret_cast<const float4*>(&as[i]);
            float4 b = *reinterpret_cast<const float4*>(&ad[i]);
            s  += v.x * a.x + v.y * a.y + v.z * a.z + v.w * a.w;
            dd += v.x * b.x + v.y * b.y + v.z * b.z + v.w * b.w;
            *reinterpret_cast<uint2*>(&yp[i]) = pack_half4(v);
        }
        S[gr * 4 + q] = s;
        D[gr * 4 + q] = dd;
    }
}

// ---- layer-2 GEMM on tensor cores (HMMA) + fused logits ---------------------
__global__ __launch_bounds__(128)
void gemm2_wmma_kernel(const __half* __restrict__ Xh,
                       const float* __restrict__ asrc, const float* __restrict__ adst,
                       __half* __restrict__ Yh,
                       float* __restrict__ S, float* __restrict__ D, int nrows) {
    extern __shared__ char smraw[];
    __half* Ah  = reinterpret_cast<__half*>(smraw);
    __half* Wh  = reinterpret_cast<__half*>(smraw) + G2_BM * G2_ALD;
    float*  stg = reinterpret_cast<float*>(smraw);

    int tid = threadIdx.x;
    int rowbase = blockIdx.x * G2_BM;

    for (int i = tid * 8; i < G2_BM * C1; i += 128 * 8) {
        int r = i >> 8, c = i & 255;
        int gr = rowbase + r;
        uint4 v = (gr < nrows)
            ? *reinterpret_cast<const uint4*>(&Xh[(size_t)gr * C1 + c])
            : make_uint4(0u, 0u, 0u, 0u);
        *reinterpret_cast<uint4*>(&Ah[r * G2_ALD + c]) = v;
    }
    for (int i = tid * 8; i < C1 * HID; i += 128 * 8) {
        int k = i >> 6, c = i & 63;
        uint4 v = *reinterpret_cast<const uint4*>(&g_w2h[i]);
        *reinterpret_cast<uint4*>(&Wh[k * G2_WLD + c]) = v;
    }
    __syncthreads();

    int w = tid >> 5;
    int r0 = w * 16;

    wmma::fragment<wmma::accumulator, 16, 16, 16, float> acc[4];
#pragma unroll
    for (int f = 0; f < 4; f++) wmma::fill_fragment(acc[f], 0.f);

#pragma unroll
    for (int kk = 0; kk < C1; kk += 16) {
        wmma::fragment<wmma::matrix_a, 16, 16, 16, __half, wmma::row_major> af;
        wmma::load_matrix_sync(af, Ah + r0 * G2_ALD + kk, G2_ALD);
#pragma unroll
        for (int f = 0; f < 4; f++) {
            wmma::fragment<wmma::matrix_b, 16, 16, 16, __half, wmma::row_major> bf;
            wmma::load_matrix_sync(bf, Wh + kk * G2_WLD + f * 16, G2_WLD);
            wmma::mma_sync(acc[f], af, bf, acc[f]);
        }
    }
    __syncthreads();
#pragma unroll
    for (int f = 0; f < 4; f++)
        wmma::store_matrix_sync(stg + r0 * G2_SLD + f * 16, acc[f],
                                G2_SLD, wmma::mem_row_major);
    __syncthreads();

    int r = tid >> 1, half = tid & 1;
    int c0 = half * 32;
    int gr = rowbase + r;
    float s = 0.f, dd = 0.f;
    if (gr < nrows) {
        const float* row = stg + r * G2_SLD + c0;
        __half* yp = Yh + (size_t)gr * HID + c0;
#pragma unroll
        for (int i = 0; i < 32; i += 4) {
            float4 v = *reinterpret_cast<const float4*>(&row[i]);
            float4 a = *reinterpret_cast<const float4*>(&asrc[c0 + i]);
            float4 b = *reinterpret_cast<const float4*>(&adst[c0 + i]);
            s  += v.x * a.x + v.y * a.y + v.z * a.z + v.w * a.w;
            dd += v.x * b.x + v.y * b.y + v.z * b.z + v.w * b.w;
            *reinterpret_cast<uint2*>(&yp[i]) = pack_half4(v);
        }
    }
    s  += __shfl_xor_sync(0xffffffffu, s, 1);
    dd += __shfl_xor_sync(0xffffffffu, dd, 1);
    if (gr < nrows && half == 0) { S[gr] = s; D[gr] = dd; }
}

// ------------------------- alpha writers (off critical path) -----------------
// alpha1: per-node warp recomputes den (same lane-order + wredsum as agg1)
// then writes normalized alphas. Depends only on CSR + gemm1 logits.
__global__ __launch_bounds__(256)
void alpha1_kernel(float* __restrict__ a1) {
    int n    = (blockIdx.x * blockDim.x + threadIdx.x) >> 5;
    int lane = threadIdx.x & 31;
    if (n >= N_NODES) return;
    int base = g_rowptr[n], end = g_rowptr[n + 1];
    float4 d = *reinterpret_cast<const float4*>(&g_d1[n * 4]);

    float4 den = make_float4(0.f, 0.f, 0.f, 0.f);
    for (int jj = base + lane; jj < end; jj += 32) {
        int2 p = g_epack[jj];
        float4 s = *reinterpret_cast<const float4*>(&g_s1[p.x * 4]);
        den.x += __expf(lrelu(s.x + d.x));
        den.y += __expf(lrelu(s.y + d.y));
        den.z += __expf(lrelu(s.z + d.z));
        den.w += __expf(lrelu(s.w + d.w));
    }
    den.x = wredsum(den.x); den.y = wredsum(den.y);
    den.z = wredsum(den.z); den.w = wredsum(den.w);
    float4 inv = make_float4(1.f / (den.x + EPS_SM), 1.f / (den.y + EPS_SM),
                             1.f / (den.z + EPS_SM), 1.f / (den.w + EPS_SM));

    for (int jj = base + lane; jj < end; jj += 32) {
        int2 p = g_epack[jj];
        float4 s = *reinterpret_cast<const float4*>(&g_s1[p.x * 4]);
        float4 al;
        al.x = __expf(lrelu(s.x + d.x)) * inv.x;
        al.y = __expf(lrelu(s.y + d.y)) * inv.y;
        al.z = __expf(lrelu(s.z + d.z)) * inv.z;
        al.w = __expf(lrelu(s.w + d.w)) * inv.w;
        *reinterpret_cast<float4*>(&a1[(size_t)p.y * 4]) = al;
    }
}

// alpha2: same for layer 2 (depends only on CSR + gemm2 logits).
__global__ __launch_bounds__(256)
void alpha2_kernel(float* __restrict__ a2) {
    int n    = (blockIdx.x * blockDim.x + threadIdx.x) >> 5;
    int lane = threadIdx.x & 31;
    if (n >= N_NODES) return;
    int base = g_rowptr[n], end = g_rowptr[n + 1];
    float dd = g_d2[n];

    float den = 0.f;
    for (int jj = base + lane; jj < end; jj += 32) {
        int2 p = g_epack[jj];
        den += __expf(lrelu(g_s2[p.x] + dd));
    }
    den = wredsum(den);
    float inv = 1.f / (den + EPS_SM);

    for (int jj = base + lane; jj < end; jj += 32) {
        int2 p = g_epack[jj];
        a2[p.y] = __expf(lrelu(g_s2[p.x] + dd)) * inv;
    }
}

// ------------------------- layer 1: chunked gather + LN + ELU ----------------
// (alpha pass removed — handled by alpha1_kernel on the side stream)
__global__ __launch_bounds__(256)
void agg1_kernel(const float* __restrict__ b1,
                 const float* __restrict__ gam, const float* __restrict__ bet) {
    __shared__ float4 se[8][32];
    int wid  = threadIdx.x >> 5;
    int lane = threadIdx.x & 31;
    int n    = (blockIdx.x * blockDim.x + threadIdx.x) >> 5;
    if (n >= N_NODES) return;
    int base = g_rowptr[n], end = g_rowptr[n + 1];
    float4 d = *reinterpret_cast<const float4*>(&g_d1[n * 4]);

    int h  = lane >> 3;
    int c0 = lane * 8;
    float acc[8];
#pragma unroll
    for (int i = 0; i < 8; i++) acc[i] = 0.f;
    float4 den = make_float4(0.f, 0.f, 0.f, 0.f);

    for (int cb = base; cb < end; cb += 32) {
        int cnt = min(32, end - cb);
        int my_src = 0;
        if (lane < cnt) {
            int2 p = g_epack[cb + lane];               // coalesced
            my_src = p.x;
            float4 s = *reinterpret_cast<const float4*>(&g_s1[p.x * 4]);
            float4 e;
            e.x = __expf(lrelu(s.x + d.x)); e.y = __expf(lrelu(s.y + d.y));
            e.z = __expf(lrelu(s.z + d.z)); e.w = __expf(lrelu(s.w + d.w));
            den.x += e.x; den.y += e.y; den.z += e.z; den.w += e.w;
            se[wid][lane] = e;
        }
        __syncwarp();
        for (int k = 0; k < cnt; k++) {
            int src  = __shfl_sync(0xffffffffu, my_src, k);
            float a  = reinterpret_cast<const float*>(&se[wid][k])[h];
            uint4 hv = *reinterpret_cast<const uint4*>(&g_h1h[(size_t)src * C1 + c0]);
            float2 f0 = __half22float2(*reinterpret_cast<__half2*>(&hv.x));
            float2 f1 = __half22float2(*reinterpret_cast<__half2*>(&hv.y));
            float2 f2 = __half22float2(*reinterpret_cast<__half2*>(&hv.z));
            float2 f3 = __half22float2(*reinterpret_cast<__half2*>(&hv.w));
            acc[0] += f0.x * a; acc[1] += f0.y * a;
            acc[2] += f1.x * a; acc[3] += f1.y * a;
            acc[4] += f2.x * a; acc[5] += f2.y * a;
            acc[6] += f3.x * a; acc[7] += f3.y * a;
        }
        __syncwarp();
    }

    den.x = wredsum(den.x); den.y = wredsum(den.y);
    den.z = wredsum(den.z); den.w = wredsum(den.w);
    float4 inv = make_float4(1.f / (den.x + EPS_SM), 1.f / (den.y + EPS_SM),
                             1.f / (den.z + EPS_SM), 1.f / (den.w + EPS_SM));

    float invh = (h == 0) ? inv.x : (h == 1) ? inv.y : (h == 2) ? inv.z : inv.w;
#pragma unroll
    for (int i = 0; i < 8; i++) acc[i] *= invh;

    // epilogue: +b1, LayerNorm(256), ELU -> g_x2h (fp16; equals gemm2's rounding)
    float4 ba = *reinterpret_cast<const float4*>(&b1[c0]);
    float4 bb = *reinterpret_cast<const float4*>(&b1[c0 + 4]);
    acc[0] += ba.x; acc[1] += ba.y; acc[2] += ba.z; acc[3] += ba.w;
    acc[4] += bb.x; acc[5] += bb.y; acc[6] += bb.z; acc[7] += bb.w;
    float sum = 0.f, sq = 0.f;
#pragma unroll
    for (int i = 0; i < 8; i++) { sum += acc[i]; sq += acc[i] * acc[i]; }
    sum = wredsum(sum); sq = wredsum(sq);
    float mu  = sum * (1.f / 256.f);
    float var = sq * (1.f / 256.f) - mu * mu;
    float rs  = rsqrtf(var + 1e-5f);
    float4 ga = *reinterpret_cast<const float4*>(&gam[c0]);
    float4 gb = *reinterpret_cast<const float4*>(&gam[c0 + 4]);
    float4 ea = *reinterpret_cast<const float4*>(&bet[c0]);
    float4 eb = *reinterpret_cast<const float4*>(&bet[c0 + 4]);
    float4 y0, y1;
    y0.x = eluf((acc[0] - mu) * rs * ga.x + ea.x);
    y0.y = eluf((acc[1] - mu) * rs * ga.y + ea.y);
    y0.z = eluf((acc[2] - mu) * rs * ga.z + ea.z);
    y0.w = eluf((acc[3] - mu) * rs * ga.w + ea.w);
    y1.x = eluf((acc[4] - mu) * rs * gb.x + eb.x);
    y1.y = eluf((acc[5] - mu) * rs * gb.y + eb.y);
    y1.z = eluf((acc[6] - mu) * rs * gb.z + eb.z);
    y1.w = eluf((acc[7] - mu) * rs * gb.w + eb.w);
    uint2 p0 = pack_half4(y0);
    uint2 p1 = pack_half4(y1);
    *reinterpret_cast<uint4*>(&g_x2h[(size_t)n * C1 + c0]) =
        make_uint4(p0.x, p0.y, p1.x, p1.y);
}

// ------------------------- layer 2: chunked gather + LN + ELU + head ---------
// (alpha pass removed — handled by alpha2_kernel on the side stream)
__global__ __launch_bounds__(256)
void agg2_kernel(const float* __restrict__ b2,
                 const float* __restrict__ g2, const float* __restrict__ e2,
                 const float* __restrict__ hW1, const float* __restrict__ hb1,
                 const float* __restrict__ hW2, const float* __restrict__ hb2,
                 float* __restrict__ out) {
    __shared__ float w1s[64 * 32];
    __shared__ float w2s[32];
    __shared__ float b1s[32];
    __shared__ float zs[8][64];
    int tid = threadIdx.x;
    for (int i = tid; i < 64 * 32; i += 256) w1s[i] = hW1[i];
    if (tid < 32) { w2s[tid] = hW2[tid]; b1s[tid] = hb1[tid]; }
    __syncthreads();

    int w    = tid >> 5;
    int lane = tid & 31;
    int n = blockIdx.x * 8 + w;
    if (n >= N_NODES) return;

    int base = g_rowptr[n], end = g_rowptr[n + 1];
    float dd = g_d2[n];

    float a0 = 0.f, a1v = 0.f, den = 0.f;
    int c0 = lane * 2;
    for (int cb = base; cb < end; cb += 32) {
        int cnt = min(32, end - cb);
        int my_src = 0; float my_e = 0.f;
        if (lane < cnt) {
            int2 p = g_epack[cb + lane];               // coalesced
            my_src = p.x;
            my_e = __expf(lrelu(g_s2[p.x] + dd));
            den += my_e;
        }
        for (int k = 0; k < cnt; k++) {
            int src = __shfl_sync(0xffffffffu, my_src, k);
            float e = __shfl_sync(0xffffffffu, my_e, k);
            unsigned u = *reinterpret_cast<const unsigned*>(&g_h2h[(size_t)src * HID + c0]);
            float2 v = __half22float2(*reinterpret_cast<__half2*>(&u));
            a0 += v.x * e; a1v += v.y * e;
        }
    }
    den = wredsum(den);
    float inv = 1.f / (den + EPS_SM);
    a0 *= inv; a1v *= inv;

    // +b2, LN(64), ELU
    a0  += b2[c0];
    a1v += b2[c0 + 1];
    float sum = wredsum(a0 + a1v);
    float sq  = wredsum(a0 * a0 + a1v * a1v);
    float mu  = sum * (1.f / 64.f);
    float var = sq * (1.f / 64.f) - mu * mu;
    float rs  = rsqrtf(var + 1e-5f);
    float y0 = eluf((a0  - mu) * rs * g2[c0]     + e2[c0]);
    float y1 = eluf((a1v - mu) * rs * g2[c0 + 1] + e2[c0 + 1]);
    zs[w][c0] = y0; zs[w][c0 + 1] = y1;
    __syncwarp();

    // MLP head: 64 -> 32 -> ReLU -> 1
    float acc = b1s[lane];
#pragma unroll
    for (int k = 0; k < 64; k++) acc += zs[w][k] * w1s[k * 32 + lane];
    acc = fmaxf(acc, 0.f);
    float p = wredsum(acc * w2s[lane]);
    if (lane == 0) out[n] = p + hb2[0];
}

// ------------------------- host launcher -------------------------------------
extern "C" void kernel_launch(void* const* d_in, const int* in_sizes, int n_in,
                              void* d_out, int out_size) {
    const float* x     = (const float*)d_in[0];
    const int*   ei    = (const int*)  d_in[1];
    const float* W1    = (const float*)d_in[2];
    const float* as1   = (const float*)d_in[3];
    const float* ad1   = (const float*)d_in[4];
    const float* b1    = (const float*)d_in[5];
    const float* W2    = (const float*)d_in[6];
    const float* as2   = (const float*)d_in[7];
    const float* ad2   = (const float*)d_in[8];
    const float* b2    = (const float*)d_in[9];
    const float* ln1g  = (const float*)d_in[10];
    const float* ln1b  = (const float*)d_in[11];
    const float* ln2g  = (const float*)d_in[12];
    const float* ln2b  = (const float*)d_in[13];
    const float* hW1   = (const float*)d_in[14];
    const float* hb1   = (const float*)d_in[15];
    const float* hW2   = (const float*)d_in[16];
    const float* hb2   = (const float*)d_in[17];
    float* out = (float*)d_out;

    // expected layout: out[N] | alpha1[ETOT*4] | alpha2[ETOT]
    size_t need = (size_t)N_NODES + (size_t)ETOT * (HEADS + 1);
    float *a1, *a2;
    if ((size_t)out_size >= need) {
        a1 = out + N_NODES;
        a2 = a1 + (size_t)ETOT * HEADS;
    } else {
        void* p;
        cudaGetSymbolAddress(&p, g_a1_fb); a1 = (float*)p;
        cudaGetSymbolAddress(&p, g_a2_fb); a2 = (float*)p;
    }

    auto cdiv = [](long a, long b) { return (int)((a + b - 1) / b); };

    float *ps1, *pd1, *ps2, *pd2;
    __half *ph1, *px2, *ph2;
    { void* p;
      cudaGetSymbolAddress(&p, g_h1h); ph1 = (__half*)p;
      cudaGetSymbolAddress(&p, g_x2h); px2 = (__half*)p;
      cudaGetSymbolAddress(&p, g_h2h); ph2 = (__half*)p;
      cudaGetSymbolAddress(&p, g_s1);  ps1 = (float*)p;
      cudaGetSymbolAddress(&p, g_d1);  pd1 = (float*)p;
      cudaGetSymbolAddress(&p, g_s2);  ps2 = (float*)p;
      cudaGetSymbolAddress(&p, g_d2);  pd2 = (float*)p;
    }

    cudaFuncSetAttribute(gemm1_wmma_kernel,
                         cudaFuncAttributeMaxDynamicSharedMemorySize, G1_SMEM);
    cudaFuncSetAttribute(gemm2_wmma_kernel,
                         cudaFuncAttributeMaxDynamicSharedMemorySize, G2_SMEM);

    // side stream: CSR build, then alpha writers (overlapped with main chain)
    cudaStream_t side;
    cudaStreamCreateWithFlags(&side, cudaStreamNonBlocking);
    cudaEvent_t evF, evJ, evG1, evG2, evEnd;
    cudaEventCreateWithFlags(&evF,   cudaEventDisableTiming);
    cudaEventCreateWithFlags(&evJ,   cudaEventDisableTiming);
    cudaEventCreateWithFlags(&evG1,  cudaEventDisableTiming);
    cudaEventCreateWithFlags(&evG2,  cudaEventDisableTiming);
    cudaEventCreateWithFlags(&evEnd, cudaEventDisableTiming);

    cudaEventRecord(evF, 0);
    cudaStreamWaitEvent(side, evF, 0);

    // ---- CSR build on side stream (independent of GEMM1) ----
    zero_cnt_kernel<<<cdiv(N_PAD / 4, 256), 256, 0, side>>>();
    hist_kernel<<<cdiv(cdiv(ETOT, 8), 256), 256, 0, side>>>(ei);
    scan_kernel<<<1, SCAN_T, 0, side>>>();
    scatter_kernel<<<cdiv(cdiv(ETOT, 8), 256), 256, 0, side>>>(ei);
    cudaEventRecord(evJ, side);

    // ---- main: W->fp16, gemm1 (concurrent with CSR) ----
    conv_w_kernel<<<cdiv((F_IN * C1 + C1 * HID) / 4, 256), 256>>>(W1, W2);
    gemm1_wmma_kernel<<<cdiv(N_NODES, G1_BM), 256, G1_SMEM>>>(
        x, as1, ad1, ph1, ps1, pd1, N_NODES);
    cudaEventRecord(evG1, 0);

    // side: alpha1 (needs CSR [same stream] + gemm1 logits) — runs under agg1
    cudaStreamWaitEvent(side, evG1, 0);
    alpha1_kernel<<<cdiv((long)N_NODES * 32, 256), 256, 0, side>>>(a1);

    // main: agg1 (needs CSR + gemm1)
    cudaStreamWaitEvent(0, evJ, 0);
    agg1_kernel<<<cdiv((long)N_NODES * 32, 256), 256>>>(b1, ln1g, ln1b);

    // main: gemm2
    gemm2_wmma_kernel<<<cdiv(N_NODES, G2_BM), 128, G2_SMEM>>>(
        px2, as2, ad2, ph2, ps2, pd2, N_NODES);
    cudaEventRecord(evG2, 0);

    // side: alpha2 (needs CSR + gemm2 logits) — runs under agg2
    cudaStreamWaitEvent(side, evG2, 0);
    alpha2_kernel<<<cdiv((long)N_NODES * 32, 256), 256, 0, side>>>(a2);
    cudaEventRecord(evEnd, side);

    // main: agg2 (LN + head -> out)
    agg2_kernel<<<cdiv(N_NODES, 8), 256>>>(b2, ln2g, ln2b, hW1, hb1, hW2, hb2, out);

    // join side stream back into the capture origin
    cudaStreamWaitEvent(0, evEnd, 0);
}

// round 15
// speedup vs baseline: 1.1090x; 1.0844x over previous
#include <cuda_runtime.h>
#include <cuda_fp16.h>
#include <mma.h>
#include <math.h>

using namespace nvcuda;

#define N_NODES 50000
#define E_EDGES 800000
#define ETOT    (E_EDGES + N_NODES)   // 850000
#define F_IN    128
#define HID     64
#define HEADS   4
#define C1      (HEADS * HID)         // 256
#define SLOPE   0.2f
#define EPS_SM  1e-16f

#define N_LO    25024                  // split point (multiple of 64)

#define SCAN_T  1024
#define SCAN_CH 52                     // 52*1024 = 53248 >= N_NODES, /4
#define N_PAD   (SCAN_T * SCAN_CH)

// wmma gemm1 tiling
#define G1_BM    64
#define G1_ALD   136
#define G1_WLD   264
#define G1_SLD   264
#define G1_SMEM  ((G1_BM * G1_ALD + 128 * G1_WLD) * 2 > G1_BM * G1_SLD * 4 ? \
                  (G1_BM * G1_ALD + 128 * G1_WLD) * 2 : G1_BM * G1_SLD * 4)

// wmma gemm2 tiling (64 rows x 64 cols x K=256, 4 warps)
#define G2_BM    64
#define G2_ALD   264
#define G2_WLD   72
#define G2_SLD   72
#define G2_SMEM  ((G2_BM * G2_ALD + 256 * G2_WLD) * 2)

// ------------------------- device scratch (no allocs allowed) ---------------
__device__ __half g_h1h[(size_t)N_NODES * C1];    // x @ W1 (fp16 storage)
__device__ __half g_x2h[(size_t)N_NODES * C1];    // layer1 out after LN/ELU (fp16)
__device__ __half g_h2h[(size_t)N_NODES * HID];   // x2 @ W2 (fp16 storage)
__device__ __half g_w1h[F_IN * C1];
__device__ __half g_w2h[C1 * HID];
__device__ float g_s1  [N_NODES * HEADS];
__device__ float g_d1  [N_NODES * HEADS];
__device__ float g_s2  [N_NODES];
__device__ float g_d2  [N_NODES];
// CSR by destination (rebuilt every launch; deterministic work)
__device__ __align__(16) int g_cnt   [N_PAD];
__device__ __align__(16) int g_rowptr[N_PAD + 4];
__device__ __align__(16) int g_wofs  [N_PAD + 4];
__device__ int2 g_epack[ETOT];                    // {src, eid} per CSR slot
// fallback alpha scratch in case d_out layout differs from expectation
__device__ float g_a1_fb[(size_t)ETOT * HEADS];
__device__ float g_a2_fb[(size_t)ETOT];

// ------------------------- helpers ------------------------------------------
__device__ __forceinline__ float lrelu(float v) { return v > 0.f ? v : SLOPE * v; }
__device__ __forceinline__ float eluf(float v)  { return v > 0.f ? v : expm1f(v); }

__device__ __forceinline__ float wredsum(float v) {
#pragma unroll
    for (int o = 16; o > 0; o >>= 1) v += __shfl_xor_sync(0xffffffffu, v, o);
    return v;
}

__device__ __forceinline__ uint2 pack_half4(float4 v) {
    __half2 h0 = __floats2half2_rn(v.x, v.y);
    __half2 h1 = __floats2half2_rn(v.z, v.w);
    return make_uint2(*reinterpret_cast<unsigned*>(&h0),
                      *reinterpret_cast<unsigned*>(&h1));
}

// ------------------------- CSR build -----------------------------------------
__global__ void hist_kernel(const int* __restrict__ ei) {
    int i0 = (blockIdx.x * blockDim.x + threadIdx.x) * 8;
    if (i0 >= ETOT) return;
    if (i0 + 8 <= E_EDGES) {
        int4 d0 = *reinterpret_cast<const int4*>(&ei[E_EDGES + i0]);
        int4 d1 = *reinterpret_cast<const int4*>(&ei[E_EDGES + i0 + 4]);
        atomicAdd(&g_cnt[d0.x], 1); atomicAdd(&g_cnt[d0.y], 1);
        atomicAdd(&g_cnt[d0.z], 1); atomicAdd(&g_cnt[d0.w], 1);
        atomicAdd(&g_cnt[d1.x], 1); atomicAdd(&g_cnt[d1.y], 1);
        atomicAdd(&g_cnt[d1.z], 1); atomicAdd(&g_cnt[d1.w], 1);
    } else {
#pragma unroll
        for (int t = 0; t < 8; t++) {
            int e = i0 + t;
            if (e < ETOT) {
                int dst = (e < E_EDGES) ? ei[E_EDGES + e] : e - E_EDGES;
                atomicAdd(&g_cnt[dst], 1);
            }
        }
    }
}

__global__ __launch_bounds__(SCAN_T) void scan_kernel() {
    __shared__ int sums[SCAN_T];
    int t = threadIdx.x;
    int lo = t * SCAN_CH;
    const int4* cp = reinterpret_cast<const int4*>(&g_cnt[lo]);
    int local = 0;
#pragma unroll
    for (int i = 0; i < SCAN_CH / 4; i++) {
        int4 c = cp[i];
        local += c.x + c.y + c.z + c.w;
    }
    sums[t] = local;
    __syncthreads();
    for (int off = 1; off < SCAN_T; off <<= 1) {
        int v = (t >= off) ? sums[t - off] : 0;
        __syncthreads();
        sums[t] += v;
        __syncthreads();
    }
    int run = sums[t] - local;
    int4* rp = reinterpret_cast<int4*>(&g_rowptr[lo]);
    int4* wp = reinterpret_cast<int4*>(&g_wofs[lo]);
#pragma unroll
    for (int i = 0; i < SCAN_CH / 4; i++) {
        int4 c = cp[i];
        int4 o;
        o.x = run; run += c.x;
        o.y = run; run += c.y;
        o.z = run; run += c.z;
        o.w = run; run += c.w;
        rp[i] = o; wp[i] = o;
    }
}

__global__ void scatter_kernel(const int* __restrict__ ei) {
    int i0 = (blockIdx.x * blockDim.x + threadIdx.x) * 8;
    if (i0 >= ETOT) return;
    if (i0 + 8 <= E_EDGES) {
        int4 s0 = *reinterpret_cast<const int4*>(&ei[i0]);
        int4 s1 = *reinterpret_cast<const int4*>(&ei[i0 + 4]);
        int4 d0 = *reinterpret_cast<const int4*>(&ei[E_EDGES + i0]);
        int4 d1 = *reinterpret_cast<const int4*>(&ei[E_EDGES + i0 + 4]);
        int sl;
        sl = atomicAdd(&g_wofs[d0.x], 1); g_epack[sl] = make_int2(s0.x, i0);
        sl = atomicAdd(&g_wofs[d0.y], 1); g_epack[sl] = make_int2(s0.y, i0 + 1);
        sl = atomicAdd(&g_wofs[d0.z], 1); g_epack[sl] = make_int2(s0.z, i0 + 2);
        sl = atomicAdd(&g_wofs[d0.w], 1); g_epack[sl] = make_int2(s0.w, i0 + 3);
        sl = atomicAdd(&g_wofs[d1.x], 1); g_epack[sl] = make_int2(s1.x, i0 + 4);
        sl = atomicAdd(&g_wofs[d1.y], 1); g_epack[sl] = make_int2(s1.y, i0 + 5);
        sl = atomicAdd(&g_wofs[d1.z], 1); g_epack[sl] = make_int2(s1.z, i0 + 6);
        sl = atomicAdd(&g_wofs[d1.w], 1); g_epack[sl] = make_int2(s1.w, i0 + 7);
    } else {
#pragma unroll
        for (int t = 0; t < 8; t++) {
            int e = i0 + t;
            if (e < ETOT) {
                int src, dst;
                if (e < E_EDGES) { src = ei[e]; dst = ei[E_EDGES + e]; }
                else             { src = dst = e - E_EDGES; }
                int slot = atomicAdd(&g_wofs[dst], 1);
                g_epack[slot] = make_int2(src, e);
            }
        }
    }
}

// ------------------------- W1+W2 fp32 -> fp16 (once per launch) --------------
__global__ void conv_w_kernel(const float* __restrict__ W1,
                              const float* __restrict__ W2) {
    int i4 = (blockIdx.x * blockDim.x + threadIdx.x) * 4;
    if (i4 < F_IN * C1) {
        float4 v = *reinterpret_cast<const float4*>(&W1[i4]);
        *reinterpret_cast<uint2*>(&g_w1h[i4]) = pack_half4(v);
    } else if (i4 < F_IN * C1 + C1 * HID) {
        int j4 = i4 - F_IN * C1;
        float4 v = *reinterpret_cast<const float4*>(&W2[j4]);
        *reinterpret_cast<uint2*>(&g_w2h[j4]) = pack_half4(v);
    }
}

// ---- layer-1 GEMM on tensor cores (HMMA) + fused logits ---------------------
__global__ __launch_bounds__(256)
void gemm1_wmma_kernel(const float* __restrict__ X,
                       const float* __restrict__ asrc, const float* __restrict__ adst,
                       __half* __restrict__ Yh,
                       float* __restrict__ S, float* __restrict__ D, int nrows) {
    extern __shared__ char smraw[];
    __half* Ah  = reinterpret_cast<__half*>(smraw);
    __half* Wh  = reinterpret_cast<__half*>(smraw) + G1_BM * G1_ALD;
    float*  stg = reinterpret_cast<float*>(smraw);

    int tid = threadIdx.x;
    int rowbase = blockIdx.x * G1_BM;

    for (int i = tid * 4; i < G1_BM * F_IN; i += 256 * 4) {
        int r = i >> 7, c = i & 127;
        int gr = rowbase + r;
        float4 v = (gr < nrows) ? *reinterpret_cast<const float4*>(&X[(size_t)gr * F_IN + c])
                                : make_float4(0.f, 0.f, 0.f, 0.f);
        *reinterpret_cast<uint2*>(&Ah[r * G1_ALD + c]) = pack_half4(v);
    }
    for (int i = tid * 8; i < F_IN * C1; i += 256 * 8) {
        int k = i >> 8, c = i & 255;
        uint4 v = *reinterpret_cast<const uint4*>(&g_w1h[i]);
        *reinterpret_cast<uint4*>(&Wh[k * G1_WLD + c]) = v;
    }
    __syncthreads();

    int w = tid >> 5;
    int r0 = (w & 3) * 16;
    int cb = (w >> 2) * 128;

    wmma::fragment<wmma::accumulator, 16, 16, 16, float> acc[8];
#pragma unroll
    for (int f = 0; f < 8; f++) wmma::fill_fragment(acc[f], 0.f);

#pragma unroll
    for (int kk = 0; kk < F_IN; kk += 16) {
        wmma::fragment<wmma::matrix_a, 16, 16, 16, __half, wmma::row_major> af;
        wmma::load_matrix_sync(af, Ah + r0 * G1_ALD + kk, G1_ALD);
#pragma unroll
        for (int f = 0; f < 8; f++) {
            wmma::fragment<wmma::matrix_b, 16, 16, 16, __half, wmma::row_major> bf;
            wmma::load_matrix_sync(bf, Wh + kk * G1_WLD + cb + f * 16, G1_WLD);
            wmma::mma_sync(acc[f], af, bf, acc[f]);
        }
    }
    __syncthreads();
#pragma unroll
    for (int f = 0; f < 8; f++)
        wmma::store_matrix_sync(stg + r0 * G1_SLD + cb + f * 16, acc[f],
                                G1_SLD, wmma::mem_row_major);
    __syncthreads();

    int r = tid >> 2, q = tid & 3;
    int gr = rowbase + r;
    if (gr < nrows) {
        const float* as = asrc + q * 64;
        const float* ad = adst + q * 64;
        const float* row = stg + r * G1_SLD + q * 64;
        __half* yp = Yh + (size_t)gr * C1 + q * 64;
        float s = 0.f, dd = 0.f;
#pragma unroll
        for (int i = 0; i < 64; i += 4) {
            float4 v = *reinterpret_cast<const float4*>(&row[i]);
            float4 a = *reinterpret_cast<const float4*>(&as[i]);
            float4 b = *reinterpret_cast<const float4*>(&ad[i]);
            s  += v.x * a.x + v.y * a.y + v.z * a.z + v.w * a.w;
            dd += v.x * b.x + v.y * b.y + v.z * b.z + v.w * b.w;
            *reinterpret_cast<uint2*>(&yp[i]) = pack_half4(v);
        }
        S[gr * 4 + q] = s;
        D[gr * 4 + q] = dd;
    }
}

// ---- layer-2 GEMM on tensor cores (HMMA) + fused logits (row-ranged) --------
__global__ __launch_bounds__(128)
void gemm2_wmma_kernel(const __half* __restrict__ Xh,
                       const float* __restrict__ asrc, const float* __restrict__ adst,
                       __half* __restrict__ Yh,
                       float* __restrict__ S, float* __restrict__ D,
                       int rowofs, int nrows) {
    extern __shared__ char smraw[];
    __half* Ah  = reinterpret_cast<__half*>(smraw);
    __half* Wh  = reinterpret_cast<__half*>(smraw) + G2_BM * G2_ALD;
    float*  stg = reinterpret_cast<float*>(smraw);

    int tid = threadIdx.x;
    int rowbase = rowofs + blockIdx.x * G2_BM;

    for (int i = tid * 8; i < G2_BM * C1; i += 128 * 8) {
        int r = i >> 8, c = i & 255;
        int gr = rowbase + r;
        uint4 v = (gr < nrows)
            ? *reinterpret_cast<const uint4*>(&Xh[(size_t)gr * C1 + c])
            : make_uint4(0u, 0u, 0u, 0u);
        *reinterpret_cast<uint4*>(&Ah[r * G2_ALD + c]) = v;
    }
    for (int i = tid * 8; i < C1 * HID; i += 128 * 8) {
        int k = i >> 6, c = i & 63;
        uint4 v = *reinterpret_cast<const uint4*>(&g_w2h[i]);
        *reinterpret_cast<uint4*>(&Wh[k * G2_WLD + c]) = v;
    }
    __syncthreads();

    int w = tid >> 5;
    int r0 = w * 16;

    wmma::fragment<wmma::accumulator, 16, 16, 16, float> acc[4];
#pragma unroll
    for (int f = 0; f < 4; f++) wmma::fill_fragment(acc[f], 0.f);

#pragma unroll
    for (int kk = 0; kk < C1; kk += 16) {
        wmma::fragment<wmma::matrix_a, 16, 16, 16, __half, wmma::row_major> af;
        wmma::load_matrix_sync(af, Ah + r0 * G2_ALD + kk, G2_ALD);
#pragma unroll
        for (int f = 0; f < 4; f++) {
            wmma::fragment<wmma::matrix_b, 16, 16, 16, __half, wmma::row_major> bf;
            wmma::load_matrix_sync(bf, Wh + kk * G2_WLD + f * 16, G2_WLD);
            wmma::mma_sync(acc[f], af, bf, acc[f]);
        }
    }
    __syncthreads();
#pragma unroll
    for (int f = 0; f < 4; f++)
        wmma::store_matrix_sync(stg + r0 * G2_SLD + f * 16, acc[f],
                                G2_SLD, wmma::mem_row_major);
    __syncthreads();

    int r = tid >> 1, half = tid & 1;
    int c0 = half * 32;
    int gr = rowbase + r;
    float s = 0.f, dd = 0.f;
    if (gr < nrows) {
        const float* row = stg + r * G2_SLD + c0;
        __half* yp = Yh + (size_t)gr * HID + c0;
#pragma unroll
        for (int i = 0; i < 32; i += 4) {
            float4 v = *reinterpret_cast<const float4*>(&row[i]);
            float4 a = *reinterpret_cast<const float4*>(&asrc[c0 + i]);
            float4 b = *reinterpret_cast<const float4*>(&adst[c0 + i]);
            s  += v.x * a.x + v.y * a.y + v.z * a.z + v.w * a.w;
            dd += v.x * b.x + v.y * b.y + v.z * b.z + v.w * b.w;
            *reinterpret_cast<uint2*>(&yp[i]) = pack_half4(v);
        }
    }
    s  += __shfl_xor_sync(0xffffffffu, s, 1);
    dd += __shfl_xor_sync(0xffffffffu, dd, 1);
    if (gr < nrows && half == 0) { S[gr] = s; D[gr] = dd; }
}

// ------------------------- alpha writers (off critical path) -----------------
__global__ __launch_bounds__(256)
void alpha1_kernel(float* __restrict__ a1) {
    int n    = (blockIdx.x * blockDim.x + threadIdx.x) >> 5;
    int lane = threadIdx.x & 31;
    if (n >= N_NODES) return;
    int base = g_rowptr[n], end = g_rowptr[n + 1];
    float4 d = *reinterpret_cast<const float4*>(&g_d1[n * 4]);

    float4 den = make_float4(0.f, 0.f, 0.f, 0.f);
    for (int jj = base + lane; jj < end; jj += 32) {
        int2 p = g_epack[jj];
        float4 s = *reinterpret_cast<const float4*>(&g_s1[p.x * 4]);
        den.x += __expf(lrelu(s.x + d.x));
        den.y += __expf(lrelu(s.y + d.y));
        den.z += __expf(lrelu(s.z + d.z));
        den.w += __expf(lrelu(s.w + d.w));
    }
    den.x = wredsum(den.x); den.y = wredsum(den.y);
    den.z = wredsum(den.z); den.w = wredsum(den.w);
    float4 inv = make_float4(1.f / (den.x + EPS_SM), 1.f / (den.y + EPS_SM),
                             1.f / (den.z + EPS_SM), 1.f / (den.w + EPS_SM));

    for (int jj = base + lane; jj < end; jj += 32) {
        int2 p = g_epack[jj];
        float4 s = *reinterpret_cast<const float4*>(&g_s1[p.x * 4]);
        float4 al;
        al.x = __expf(lrelu(s.x + d.x)) * inv.x;
        al.y = __expf(lrelu(s.y + d.y)) * inv.y;
        al.z = __expf(lrelu(s.z + d.z)) * inv.z;
        al.w = __expf(lrelu(s.w + d.w)) * inv.w;
        *reinterpret_cast<float4*>(&a1[(size_t)p.y * 4]) = al;
    }
}

__global__ __launch_bounds__(256)
void alpha2_kernel(float* __restrict__ a2) {
    int n    = (blockIdx.x * blockDim.x + threadIdx.x) >> 5;
    int lane = threadIdx.x & 31;
    if (n >= N_NODES) return;
    int base = g_rowptr[n], end = g_rowptr[n + 1];
    float dd = g_d2[n];

    float den = 0.f;
    for (int jj = base + lane; jj < end; jj += 32) {
        int2 p = g_epack[jj];
        den += __expf(lrelu(g_s2[p.x] + dd));
    }
    den = wredsum(den);
    float inv = 1.f / (den + EPS_SM);

    for (int jj = base + lane; jj < end; jj += 32) {
        int2 p = g_epack[jj];
        a2[p.y] = __expf(lrelu(g_s2[p.x] + dd)) * inv;
    }
}

// ------------------------- layer 1: chunked gather + LN + ELU (node-ranged) --
__global__ __launch_bounds__(256)
void agg1_kernel(const float* __restrict__ b1,
                 const float* __restrict__ gam, const float* __restrict__ bet,
                 int nofs, int nend) {
    __shared__ float4 se[8][32];
    int wid  = threadIdx.x >> 5;
    int lane = threadIdx.x & 31;
    int n    = nofs + ((blockIdx.x * blockDim.x + threadIdx.x) >> 5);
    if (n >= nend) return;
    int base = g_rowptr[n], end = g_rowptr[n + 1];
    float4 d = *reinterpret_cast<const float4*>(&g_d1[n * 4]);

    int h  = lane >> 3;
    int c0 = lane * 8;
    float acc[8];
#pragma unroll
    for (int i = 0; i < 8; i++) acc[i] = 0.f;
    float4 den = make_float4(0.f, 0.f, 0.f, 0.f);

    for (int cb = base; cb < end; cb += 32) {
        int cnt = min(32, end - cb);
        int my_src = 0;
        if (lane < cnt) {
            int2 p = g_epack[cb + lane];               // coalesced
            my_src = p.x;
            float4 s = *reinterpret_cast<const float4*>(&g_s1[p.x * 4]);
            float4 e;
            e.x = __expf(lrelu(s.x + d.x)); e.y = __expf(lrelu(s.y + d.y));
            e.z = __expf(lrelu(s.z + d.z)); e.w = __expf(lrelu(s.w + d.w));
            den.x += e.x; den.y += e.y; den.z += e.z; den.w += e.w;
            se[wid][lane] = e;
        }
        __syncwarp();
        for (int k = 0; k < cnt; k++) {
            int src  = __shfl_sync(0xffffffffu, my_src, k);
            float a  = reinterpret_cast<const float*>(&se[wid][k])[h];
            uint4 hv = *reinterpret_cast<const uint4*>(&g_h1h[(size_t)src * C1 + c0]);
            float2 f0 = __half22float2(*reinterpret_cast<__half2*>(&hv.x));
            float2 f1 = __half22float2(*reinterpret_cast<__half2*>(&hv.y));
            float2 f2 = __half22float2(*reinterpret_cast<__half2*>(&hv.z));
            float2 f3 = __half22float2(*reinterpret_cast<__half2*>(&hv.w));
            acc[0] += f0.x * a; acc[1] += f0.y * a;
            acc[2] += f1.x * a; acc[3] += f1.y * a;
            acc[4] += f2.x * a; acc[5] += f2.y * a;
            acc[6] += f3.x * a; acc[7] += f3.y * a;
        }
        __syncwarp();
    }

    den.x = wredsum(den.x); den.y = wredsum(den.y);
    den.z = wredsum(den.z); den.w = wredsum(den.w);
    float4 inv = make_float4(1.f / (den.x + EPS_SM), 1.f / (den.y + EPS_SM),
                             1.f / (den.z + EPS_SM), 1.f / (den.w + EPS_SM));

    float invh = (h == 0) ? inv.x : (h == 1) ? inv.y : (h == 2) ? inv.z : inv.w;
#pragma unroll
    for (int i = 0; i < 8; i++) acc[i] *= invh;

    // epilogue: +b1, LayerNorm(256), ELU -> g_x2h
    float4 ba = *reinterpret_cast<const float4*>(&b1[c0]);
    float4 bb = *reinterpret_cast<const float4*>(&b1[c0 + 4]);
    acc[0] += ba.x; acc[1] += ba.y; acc[2] += ba.z; acc[3] += ba.w;
    acc[4] += bb.x; acc[5] += bb.y; acc[6] += bb.z; acc[7] += bb.w;
    float sum = 0.f, sq = 0.f;
#pragma unroll
    for (int i = 0; i < 8; i++) { sum += acc[i]; sq += acc[i] * acc[i]; }
    sum = wredsum(sum); sq = wredsum(sq);
    float mu  = sum * (1.f / 256.f);
    float var = sq * (1.f / 256.f) - mu * mu;
    float rs  = rsqrtf(var + 1e-5f);
    float4 ga = *reinterpret_cast<const float4*>(&gam[c0]);
    float4 gb = *reinterpret_cast<const float4*>(&gam[c0 + 4]);
    float4 ea = *reinterpret_cast<const float4*>(&bet[c0]);
    float4 eb = *reinterpret_cast<const float4*>(&bet[c0 + 4]);
    float4 y0, y1;
    y0.x = eluf((acc[0] - mu) * rs * ga.x + ea.x);
    y0.y = eluf((acc[1] - mu) * rs * ga.y + ea.y);
    y0.z = eluf((acc[2] - mu) * rs * ga.z + ea.z);
    y0.w = eluf((acc[3] - mu) * rs * ga.w + ea.w);
    y1.x = eluf((acc[4] - mu) * rs * gb.x + eb.x);
    y1.y = eluf((acc[5] - mu) * rs * gb.y + eb.y);
    y1.z = eluf((acc[6] - mu) * rs * gb.z + eb.z);
    y1.w = eluf((acc[7] - mu) * rs * gb.w + eb.w);
    uint2 p0 = pack_half4(y0);
    uint2 p1 = pack_half4(y1);
    *reinterpret_cast<uint4*>(&g_x2h[(size_t)n * C1 + c0]) =
        make_uint4(p0.x, p0.y, p1.x, p1.y);
}

// ------------------------- layer 2: chunked gather + LN + ELU + head ---------
__global__ __launch_bounds__(256)
void agg2_kernel(const float* __restrict__ b2,
                 const float* __restrict__ g2, const float* __restrict__ e2,
                 const float* __restrict__ hW1, const float* __restrict__ hb1,
                 const float* __restrict__ hW2, const float* __restrict__ hb2,
                 float* __restrict__ out) {
    __shared__ float w1s[64 * 32];
    __shared__ float w2s[32];
    __shared__ float b1s[32];
    __shared__ float zs[8][64];
    int tid = threadIdx.x;
    for (int i = tid; i < 64 * 32; i += 256) w1s[i] = hW1[i];
    if (tid < 32) { w2s[tid] = hW2[tid]; b1s[tid] = hb1[tid]; }
    __syncthreads();

    int w    = tid >> 5;
    int lane = tid & 31;
    int n = blockIdx.x * 8 + w;
    if (n >= N_NODES) return;

    int base = g_rowptr[n], end = g_rowptr[n + 1];
    float dd = g_d2[n];

    float a0 = 0.f, a1v = 0.f, den = 0.f;
    int c0 = lane * 2;
    for (int cb = base; cb < end; cb += 32) {
        int cnt = min(32, end - cb);
        int my_src = 0; float my_e = 0.f;
        if (lane < cnt) {
            int2 p = g_epack[cb + lane];               // coalesced
            my_src = p.x;
            my_e = __expf(lrelu(g_s2[p.x] + dd));
            den += my_e;
        }
        for (int k = 0; k < cnt; k++) {
            int src = __shfl_sync(0xffffffffu, my_src, k);
            float e = __shfl_sync(0xffffffffu, my_e, k);
            unsigned u = *reinterpret_cast<const unsigned*>(&g_h2h[(size_t)src * HID + c0]);
            float2 v = __half22float2(*reinterpret_cast<__half2*>(&u));
            a0 += v.x * e; a1v += v.y * e;
        }
    }
    den = wredsum(den);
    float inv = 1.f / (den + EPS_SM);
    a0 *= inv; a1v *= inv;

    // +b2, LN(64), ELU
    a0  += b2[c0];
    a1v += b2[c0 + 1];
    float sum = wredsum(a0 + a1v);
    float sq  = wredsum(a0 * a0 + a1v * a1v);
    float mu  = sum * (1.f / 64.f);
    float var = sq * (1.f / 64.f) - mu * mu;
    float rs  = rsqrtf(var + 1e-5f);
    float y0 = eluf((a0  - mu) * rs * g2[c0]     + e2[c0]);
    float y1 = eluf((a1v - mu) * rs * g2[c0 + 1] + e2[c0 + 1]);
    zs[w][c0] = y0; zs[w][c0 + 1] = y1;
    __syncwarp();

    // MLP head: 64 -> 32 -> ReLU -> 1
    float acc = b1s[lane];
#pragma unroll
    for (int k = 0; k < 64; k++) acc += zs[w][k] * w1s[k * 32 + lane];
    acc = fmaxf(acc, 0.f);
    float p = wredsum(acc * w2s[lane]);
    if (lane == 0) out[n] = p + hb2[0];
}

// ------------------------- host launcher -------------------------------------
extern "C" void kernel_launch(void* const* d_in, const int* in_sizes, int n_in,
                              void* d_out, int out_size) {
    const float* x     = (const float*)d_in[0];
    const int*   ei    = (const int*)  d_in[1];
    const float* W1    = (const float*)d_in[2];
    const float* as1   = (const float*)d_in[3];
    const float* ad1   = (const float*)d_in[4];
    const float* b1    = (const float*)d_in[5];
    const float* W2    = (const float*)d_in[6];
    const float* as2   = (const float*)d_in[7];
    const float* ad2   = (const float*)d_in[8];
    const float* b2    = (const float*)d_in[9];
    const float* ln1g  = (const float*)d_in[10];
    const float* ln1b  = (const float*)d_in[11];
    const float* ln2g  = (const float*)d_in[12];
    const float* ln2b  = (const float*)d_in[13];
    const float* hW1   = (const float*)d_in[14];
    const float* hb1   = (const float*)d_in[15];
    const float* hW2   = (const float*)d_in[16];
    const float* hb2   = (const float*)d_in[17];
    float* out = (float*)d_out;

    // expected layout: out[N] | alpha1[ETOT*4] | alpha2[ETOT]
    size_t need = (size_t)N_NODES + (size_t)ETOT * (HEADS + 1);
    float *a1, *a2;
    if ((size_t)out_size >= need) {
        a1 = out + N_NODES;
        a2 = a1 + (size_t)ETOT * HEADS;
    } else {
        void* p;
        cudaGetSymbolAddress(&p, g_a1_fb); a1 = (float*)p;
        cudaGetSymbolAddress(&p, g_a2_fb); a2 = (float*)p;
    }

    auto cdiv = [](long a, long b) { return (int)((a + b - 1) / b); };

    float *ps1, *pd1, *ps2, *pd2;
    __half *ph1, *px2, *ph2;
    void* pcnt;
    { void* p;
      cudaGetSymbolAddress(&p, g_h1h); ph1 = (__half*)p;
      cudaGetSymbolAddress(&p, g_x2h); px2 = (__half*)p;
      cudaGetSymbolAddress(&p, g_h2h); ph2 = (__half*)p;
      cudaGetSymbolAddress(&p, g_s1);  ps1 = (float*)p;
      cudaGetSymbolAddress(&p, g_d1);  pd1 = (float*)p;
      cudaGetSymbolAddress(&p, g_s2);  ps2 = (float*)p;
      cudaGetSymbolAddress(&p, g_d2);  pd2 = (float*)p;
      cudaGetSymbolAddress(&pcnt, g_cnt);
    }

    cudaFuncSetAttribute(gemm1_wmma_kernel,
                         cudaFuncAttributeMaxDynamicSharedMemorySize, G1_SMEM);
    cudaFuncSetAttribute(gemm2_wmma_kernel,
                         cudaFuncAttributeMaxDynamicSharedMemorySize, G2_SMEM);

    // side stream: CSR build, alpha writers, gemm2_lo (overlap with main chain)
    cudaStream_t side;
    cudaStreamCreateWithFlags(&side, cudaStreamNonBlocking);
    cudaEvent_t evF, evJ, evG1, evA1lo, evG2lo, evG2, evEnd;
    cudaEventCreateWithFlags(&evF,    cudaEventDisableTiming);
    cudaEventCreateWithFlags(&evJ,    cudaEventDisableTiming);
    cudaEventCreateWithFlags(&evG1,   cudaEventDisableTiming);
    cudaEventCreateWithFlags(&evA1lo, cudaEventDisableTiming);
    cudaEventCreateWithFlags(&evG2lo, cudaEventDisableTiming);
    cudaEventCreateWithFlags(&evG2,   cudaEventDisableTiming);
    cudaEventCreateWithFlags(&evEnd,  cudaEventDisableTiming);

    cudaEventRecord(evF, 0);
    cudaStreamWaitEvent(side, evF, 0);

    // ---- CSR build on side stream (memset node replaces zero kernel) ----
    cudaMemsetAsync(pcnt, 0, (size_t)N_PAD * sizeof(int), side);
    hist_kernel<<<cdiv(cdiv(ETOT, 8), 256), 256, 0, side>>>(ei);
    scan_kernel<<<1, SCAN_T, 0, side>>>();
    scatter_kernel<<<cdiv(cdiv(ETOT, 8), 256), 256, 0, side>>>(ei);
    cudaEventRecord(evJ, side);

    // ---- main: W->fp16, gemm1 (concurrent with CSR) ----
    conv_w_kernel<<<cdiv((F_IN * C1 + C1 * HID) / 4, 256), 256>>>(W1, W2);
    gemm1_wmma_kernel<<<cdiv(N_NODES, G1_BM), 256, G1_SMEM>>>(
        x, as1, ad1, ph1, ps1, pd1, N_NODES);
    cudaEventRecord(evG1, 0);

    // side: alpha1 (needs CSR + gemm1 logits) — overlaps agg1
    cudaStreamWaitEvent(side, evG1, 0);
    alpha1_kernel<<<cdiv((long)N_NODES * 32, 256), 256, 0, side>>>(a1);

    // main: agg1 split into halves; gemm2_lo pipelines under agg1_hi
    cudaStreamWaitEvent(0, evJ, 0);
    agg1_kernel<<<cdiv((long)N_LO * 32, 256), 256>>>(b1, ln1g, ln1b, 0, N_LO);
    cudaEventRecord(evA1lo, 0);

    // side: gemm2 on rows [0, N_LO) — concurrent with agg1_hi (different pipes)
    cudaStreamWaitEvent(side, evA1lo, 0);
    gemm2_wmma_kernel<<<N_LO / G2_BM, 128, G2_SMEM, side>>>(
        px2, as2, ad2, ph2, ps2, pd2, 0, N_LO);
    cudaEventRecord(evG2lo, side);

    // main: agg1_hi, then gemm2_hi
    agg1_kernel<<<cdiv((long)(N_NODES - N_LO) * 32, 256), 256>>>(
        b1, ln1g, ln1b, N_LO, N_NODES);
    gemm2_wmma_kernel<<<cdiv(N_NODES - N_LO, G2_BM), 128, G2_SMEM>>>(
        px2, as2, ad2, ph2, ps2, pd2, N_LO, N_NODES);
    cudaStreamWaitEvent(0, evG2lo, 0);   // both halves of h2/s2/d2 ready
    cudaEventRecord(evG2, 0);

    // side: alpha2 (needs full s2/d2) — overlaps agg2
    cudaStreamWaitEvent(side, evG2, 0);
    alpha2_kernel<<<cdiv((long)N_NODES * 32, 256), 256, 0, side>>>(a2);
    cudaEventRecord(evEnd, side);

    // main: agg2 (LN + head -> out)
    agg2_kernel<<<cdiv(N_NODES, 8), 256>>>(b2, ln2g, ln2b, hW1, hb1, hW2, hb2, out);

    // join side stream back into the capture origin
    cudaStreamWaitEvent(0, evEnd, 0);
}